// round 2
// baseline (speedup 1.0000x reference)
#include <cuda_runtime.h>
#include <math.h>

// Problem constants
static const int NN  = 50000;     // nodes
static const int EE  = 1600000;   // edges (before self loops)
static const int ET  = 1650000;   // edges + self loops
static const int GG  = 512;       // graphs

// ---------------- scratch (device globals; allocation-free) ----------------
__device__ float g_h1[NN * 128];
__device__ float g_out1[NN * 128];
__device__ float g_as1[NN * 4];
__device__ float g_ad1[NN * 4];
__device__ float g_den1[NN * 4];
__device__ float g_ex1[ET * 4];
__device__ float g_h2[NN * 32];
__device__ float g_as2[NN];
__device__ float g_ad2[NN];
__device__ float g_den2[NN];
__device__ float g_ex2[ET];
__device__ float g_out2[NN * 32];
__device__ float g_pool[GG * 32];
__device__ float g_cnt[GG];

__device__ __forceinline__ void red_add_v4(float* p, float4 v) {
    asm volatile("red.global.add.v4.f32 [%0], {%1,%2,%3,%4};"
                 :: "l"(p), "f"(v.x), "f"(v.y), "f"(v.z), "f"(v.w) : "memory");
}

__device__ __forceinline__ float elu1(float x) {
    return x > 0.f ? x : (__expf(x) - 1.f);
}
__device__ __forceinline__ float lrelu(float x) {
    return x > 0.f ? x : 0.2f * x;
}

__device__ __forceinline__ int clampN(int v) {
    return v < 0 ? 0 : (v >= NN ? NN - 1 : v);
}

// ---------------- kernel 1: h1 = x @ W1 ; as1/ad1 per node per head --------
// blockDim 256 (8 warps), 64 rows/block, dyn smem: W (64KB) + x rows (32KB)
extern "C" __global__ void k_gemm1(const float* __restrict__ x,
                                   const float* __restrict__ W,
                                   const float* __restrict__ a_src,
                                   const float* __restrict__ a_dst) {
    extern __shared__ float smem[];
    float* W_s = smem;             // 128*128
    float* x_s = smem + 128 * 128; // 64*128
    int tid = threadIdx.x;
    int warp = tid >> 5, lane = tid & 31;
    int row0 = blockIdx.x * 64;

    for (int i = tid; i < 128 * 128 / 4; i += 256)
        ((float4*)W_s)[i] = ((const float4*)W)[i];
    for (int i = tid; i < 64 * 128 / 4; i += 256) {
        int r = i >> 5;
        int c4 = i & 31;
        int gr = row0 + r;
        float4 v = make_float4(0.f, 0.f, 0.f, 0.f);
        if (gr < NN) v = ((const float4*)x)[gr * 32 + c4];
        ((float4*)x_s)[i] = v;
    }
    __syncthreads();

    float4 acc[8];
#pragma unroll
    for (int r = 0; r < 8; r++) acc[r] = make_float4(0.f, 0.f, 0.f, 0.f);

    const float* xw = x_s + warp * 8 * 128;
#pragma unroll 4
    for (int k = 0; k < 128; k++) {
        float4 wv = *(const float4*)(W_s + k * 128 + lane * 4);
#pragma unroll
        for (int r = 0; r < 8; r++) {
            float xv = xw[r * 128 + k];
            acc[r].x += xv * wv.x;
            acc[r].y += xv * wv.y;
            acc[r].z += xv * wv.z;
            acc[r].w += xv * wv.w;
        }
    }

    float4 av = ((const float4*)a_src)[lane];
    float4 dv = ((const float4*)a_dst)[lane];
#pragma unroll
    for (int r = 0; r < 8; r++) {
        int row = row0 + warp * 8 + r;
        if (row < NN) {
            ((float4*)g_h1)[row * 32 + lane] = acc[r];
            float ps = acc[r].x * av.x + acc[r].y * av.y + acc[r].z * av.z + acc[r].w * av.w;
            float pd = acc[r].x * dv.x + acc[r].y * dv.y + acc[r].z * dv.z + acc[r].w * dv.w;
            ps += __shfl_down_sync(0xffffffffu, ps, 4, 8);
            ps += __shfl_down_sync(0xffffffffu, ps, 2, 8);
            ps += __shfl_down_sync(0xffffffffu, ps, 1, 8);
            pd += __shfl_down_sync(0xffffffffu, pd, 4, 8);
            pd += __shfl_down_sync(0xffffffffu, pd, 2, 8);
            pd += __shfl_down_sync(0xffffffffu, pd, 1, 8);
            if ((lane & 7) == 0) {
                g_as1[row * 4 + (lane >> 3)] = ps;
                g_ad1[row * 4 + (lane >> 3)] = pd;
            }
        }
    }
}

// ---------------- kernel 2: edge logits layer1 (no max-sub; exp + den) -----
extern "C" __global__ void k_edge1a(const int* __restrict__ ei) {
    int e = blockIdx.x * blockDim.x + threadIdx.x;
    if (e >= ET) return;
    int s, d;
    if (e < EE) { s = clampN(ei[e]); d = clampN(ei[EE + e]); }
    else        { s = d = e - EE; }
    float4 a = ((const float4*)g_as1)[s];
    float4 b = ((const float4*)g_ad1)[d];
    float4 ex;
    ex.x = __expf(lrelu(a.x + b.x));
    ex.y = __expf(lrelu(a.y + b.y));
    ex.z = __expf(lrelu(a.z + b.z));
    ex.w = __expf(lrelu(a.w + b.w));
    ((float4*)g_ex1)[e] = ex;
    red_add_v4(&g_den1[d * 4], ex);
}

// ---------------- kernel 3: layer1 aggregation (warp per edge) -------------
extern "C" __global__ void k_edge1b(const int* __restrict__ ei) {
    int idx = blockIdx.x * blockDim.x + threadIdx.x;
    int e = idx >> 5;
    int lane = idx & 31;
    if (e >= ET) return;
    int s, d;
    if (e < EE) { s = clampN(ei[e]); d = clampN(ei[EE + e]); }
    else        { s = d = e - EE; }
    int head = lane >> 3;
    float alpha = g_ex1[e * 4 + head] * __frcp_rn(g_den1[d * 4 + head]);
    float4 hv = ((const float4*)g_h1)[s * 32 + lane];
    float4 v = make_float4(hv.x * alpha, hv.y * alpha, hv.z * alpha, hv.w * alpha);
    red_add_v4(&g_out1[d * 128 + lane * 4], v);
}

// ---------------- kernel 4: y=elu(out1+b1); h2=y@W2; as2/ad2 ---------------
extern "C" __global__ void k_post1(const float* __restrict__ W2,
                                   const float* __restrict__ b1,
                                   const float* __restrict__ a_src2,
                                   const float* __restrict__ a_dst2) {
    __shared__ float W2t[32 * 132];   // [c][k], padded stride 132
    __shared__ float y_s[8][128];
    int tid = threadIdx.x, warp = tid >> 5, lane = tid & 31;
    for (int i = tid; i < 4096; i += 256) {
        int k = i >> 5, c = i & 31;
        W2t[c * 132 + k] = W2[i];
    }
    __syncthreads();
    int node = blockIdx.x * 8 + warp;
    if (node >= NN) return;
    float4 v = ((const float4*)g_out1)[node * 32 + lane];
    float4 bb = ((const float4*)b1)[lane];
    v.x = elu1(v.x + bb.x);
    v.y = elu1(v.y + bb.y);
    v.z = elu1(v.z + bb.z);
    v.w = elu1(v.w + bb.w);
    ((float4*)(y_s[warp]))[lane] = v;
    __syncwarp();
    float acc = 0.f;
    const float* yr = y_s[warp];
    const float* wr = W2t + lane * 132;
#pragma unroll
    for (int k = 0; k < 128; k += 4) {
        float4 yv = *(const float4*)(yr + k);
        float4 wv = *(const float4*)(wr + k);
        acc += yv.x * wv.x + yv.y * wv.y + yv.z * wv.z + yv.w * wv.w;
    }
    g_h2[node * 32 + lane] = acc;
    float ps = acc * a_src2[lane];
    float pd = acc * a_dst2[lane];
#pragma unroll
    for (int off = 16; off > 0; off >>= 1) {
        ps += __shfl_down_sync(0xffffffffu, ps, off);
        pd += __shfl_down_sync(0xffffffffu, pd, off);
    }
    if (lane == 0) { g_as2[node] = ps; g_ad2[node] = pd; }
}

// ---------------- kernel 5: edge logits layer2 -----------------------------
extern "C" __global__ void k_edge2a(const int* __restrict__ ei) {
    int e = blockIdx.x * blockDim.x + threadIdx.x;
    if (e >= ET) return;
    int s, d;
    if (e < EE) { s = clampN(ei[e]); d = clampN(ei[EE + e]); }
    else        { s = d = e - EE; }
    float ex = __expf(lrelu(g_as2[s] + g_ad2[d]));
    g_ex2[e] = ex;
    atomicAdd(&g_den2[d], ex);
}

// ---------------- kernel 6: layer2 aggregation (8 lanes per edge) ----------
extern "C" __global__ void k_edge2b(const int* __restrict__ ei) {
    int idx = blockIdx.x * blockDim.x + threadIdx.x;
    int e = idx >> 3;
    int t = idx & 7;
    if (e >= ET) return;
    int s, d;
    if (e < EE) { s = clampN(ei[e]); d = clampN(ei[EE + e]); }
    else        { s = d = e - EE; }
    float alpha = g_ex2[e] * __frcp_rn(g_den2[d]);
    float4 hv = ((const float4*)g_h2)[s * 8 + t];
    float4 v = make_float4(hv.x * alpha, hv.y * alpha, hv.z * alpha, hv.w * alpha);
    red_add_v4(&g_out2[d * 32 + t * 4], v);
}

// ---------------- kernel 7: elu(out2+b2) -> mean-pool accumulation ---------
extern "C" __global__ void k_pool(const int* __restrict__ batch,
                                  const float* __restrict__ b2) {
    int idx = blockIdx.x * blockDim.x + threadIdx.x;
    if (idx >= NN * 32) return;
    int n = idx >> 5;
    int c = idx & 31;
    float v = elu1(g_out2[idx] + b2[c]);
    int g = batch[n];
    g = g < 0 ? 0 : (g >= GG ? GG - 1 : g);
    atomicAdd(&g_pool[g * 32 + c], v);
    if (c == 0) atomicAdd(&g_cnt[g], 1.0f);
}

// ---------------- kernel 8: classifier head (warp per graph) ---------------
extern "C" __global__ void k_final(const float* __restrict__ Wc1,
                                   const float* __restrict__ bc1,
                                   const float* __restrict__ Wc2,
                                   const float* __restrict__ bc2,
                                   float* __restrict__ out) {
    __shared__ float p_s[4][32];
    int tid = threadIdx.x, warp = tid >> 5, lane = tid & 31;
    int g = blockIdx.x * 4 + warp;
    if (g >= GG) return;
    float invc = 1.0f / g_cnt[g];
    float p = g_pool[g * 32 + lane] * invc;
    p_s[warp][lane] = p;
    __syncwarp();
    float z = 0.f;
    if (lane < 16) {
        z = bc1[lane];
#pragma unroll
        for (int c = 0; c < 32; c++)
            z += p_s[warp][c] * Wc1[c * 16 + lane];
        z = fmaxf(z, 0.f) * Wc2[lane];
    }
#pragma unroll
    for (int off = 16; off > 0; off >>= 1)
        z += __shfl_down_sync(0xffffffffu, z, off);
    if (lane == 0) out[g] = z + bc2[0];
}

// ---------------- launch -----------------------------------------------------
extern "C" void kernel_launch(void* const* d_in, const int* in_sizes, int n_in,
                              void* d_out, int out_size) {
    const float* x     = (const float*)d_in[0];
    const int*   ei    = (const int*)d_in[1];
    // d_in[2] = edge_attr (unused by the reference network)
    const int*   batch = (const int*)d_in[3];
    const float* W1   = (const float*)d_in[4];
    const float* as1  = (const float*)d_in[5];
    const float* ad1  = (const float*)d_in[6];
    const float* b1   = (const float*)d_in[7];
    const float* W2   = (const float*)d_in[8];
    const float* as2  = (const float*)d_in[9];
    const float* ad2  = (const float*)d_in[10];
    const float* b2   = (const float*)d_in[11];
    const float* Wc1  = (const float*)d_in[12];
    const float* bc1  = (const float*)d_in[13];
    const float* Wc2  = (const float*)d_in[14];
    const float* bc2  = (const float*)d_in[15];
    float* out = (float*)d_out;

    // zero accumulators
    void *p_out1, *p_den1, *p_out2, *p_den2, *p_pool, *p_cnt;
    cudaGetSymbolAddress(&p_out1, g_out1);
    cudaGetSymbolAddress(&p_den1, g_den1);
    cudaGetSymbolAddress(&p_out2, g_out2);
    cudaGetSymbolAddress(&p_den2, g_den2);
    cudaGetSymbolAddress(&p_pool, g_pool);
    cudaGetSymbolAddress(&p_cnt,  g_cnt);
    cudaMemsetAsync(p_out1, 0, sizeof(float) * NN * 128);
    cudaMemsetAsync(p_den1, 0, sizeof(float) * NN * 4);
    cudaMemsetAsync(p_out2, 0, sizeof(float) * NN * 32);
    cudaMemsetAsync(p_den2, 0, sizeof(float) * NN);
    cudaMemsetAsync(p_pool, 0, sizeof(float) * GG * 32);
    cudaMemsetAsync(p_cnt,  0, sizeof(float) * GG);

    cudaFuncSetAttribute(k_gemm1, cudaFuncAttributeMaxDynamicSharedMemorySize, 98304);

    k_gemm1<<<(NN + 63) / 64, 256, 98304>>>(x, W1, as1, ad1);
    k_edge1a<<<(ET + 255) / 256, 256>>>(ei);
    {
        long long threads = (long long)ET * 32;
        k_edge1b<<<(int)((threads + 255) / 256), 256>>>(ei);
    }
    k_post1<<<(NN + 7) / 8, 256>>>(W2, b1, as2, ad2);
    k_edge2a<<<(ET + 255) / 256, 256>>>(ei);
    {
        long long threads = (long long)ET * 8;
        k_edge2b<<<(int)((threads + 255) / 256), 256>>>(ei);
    }
    k_pool<<<(NN * 32 + 255) / 256, 256>>>(batch, b2);
    k_final<<<GG / 4, 128>>>(Wc1, bc1, Wc2, bc2, out);
}

// round 17
// speedup vs baseline: 1.4924x; 1.4924x over previous
#include <cuda_runtime.h>
#include <math.h>

static const int NN  = 50000;     // nodes
static const int EE  = 1600000;   // edges (before self loops)
static const int ET  = 1650000;   // edges + self loops
static const int GG  = 512;       // graphs

// ---------------- scratch (device globals; allocation-free) ----------------
__device__ float g_h1[NN * 128];   // layer1 linear output
__device__ float g_y1[NN * 128];   // elu(agg1 + b1)
__device__ float g_as1[NN * 4];
__device__ float g_ad1[NN * 4];
__device__ float g_h2[NN * 32];
__device__ float g_as2[NN];
__device__ float g_ad2[NN];
__device__ float g_z[NN * 32];     // elu(agg2 + b2)
__device__ int   g_deg[NN];
__device__ int   g_cur[NN];
__device__ int   g_rs[NN + 1];     // CSR row starts
__device__ int   g_csr[ET];        // src per slot, bucketed by dst

__device__ __forceinline__ float elu1(float x) {
    return x > 0.f ? x : (__expf(x) - 1.f);
}
__device__ __forceinline__ float lrelu(float x) {
    return x > 0.f ? x : 0.2f * x;
}
__device__ __forceinline__ int clampN(int v) {
    return v < 0 ? 0 : (v >= NN ? NN - 1 : v);
}

// ---------------- kernel 1: h1 = x @ W1 ; as1/ad1 per node per head --------
extern "C" __global__ void k_gemm1(const float* __restrict__ x,
                                   const float* __restrict__ W,
                                   const float* __restrict__ a_src,
                                   const float* __restrict__ a_dst) {
    extern __shared__ float smem[];
    float* W_s = smem;             // 128*128
    float* x_s = smem + 128 * 128; // 64*128
    int tid = threadIdx.x;
    int warp = tid >> 5, lane = tid & 31;
    int row0 = blockIdx.x * 64;

    for (int i = tid; i < 128 * 128 / 4; i += 256)
        ((float4*)W_s)[i] = ((const float4*)W)[i];
    for (int i = tid; i < 64 * 128 / 4; i += 256) {
        int r = i >> 5;
        int c4 = i & 31;
        int gr = row0 + r;
        float4 v = make_float4(0.f, 0.f, 0.f, 0.f);
        if (gr < NN) v = ((const float4*)x)[gr * 32 + c4];
        ((float4*)x_s)[i] = v;
    }
    __syncthreads();

    float4 acc[8];
#pragma unroll
    for (int r = 0; r < 8; r++) acc[r] = make_float4(0.f, 0.f, 0.f, 0.f);

    const float* xw = x_s + warp * 8 * 128;
#pragma unroll 4
    for (int k = 0; k < 128; k++) {
        float4 wv = *(const float4*)(W_s + k * 128 + lane * 4);
#pragma unroll
        for (int r = 0; r < 8; r++) {
            float xv = xw[r * 128 + k];
            acc[r].x += xv * wv.x;
            acc[r].y += xv * wv.y;
            acc[r].z += xv * wv.z;
            acc[r].w += xv * wv.w;
        }
    }

    float4 av = ((const float4*)a_src)[lane];
    float4 dv = ((const float4*)a_dst)[lane];
#pragma unroll
    for (int r = 0; r < 8; r++) {
        int row = row0 + warp * 8 + r;
        if (row < NN) {
            ((float4*)g_h1)[row * 32 + lane] = acc[r];
            float ps = acc[r].x * av.x + acc[r].y * av.y + acc[r].z * av.z + acc[r].w * av.w;
            float pd = acc[r].x * dv.x + acc[r].y * dv.y + acc[r].z * dv.z + acc[r].w * dv.w;
            ps += __shfl_down_sync(0xffffffffu, ps, 4, 8);
            ps += __shfl_down_sync(0xffffffffu, ps, 2, 8);
            ps += __shfl_down_sync(0xffffffffu, ps, 1, 8);
            pd += __shfl_down_sync(0xffffffffu, pd, 4, 8);
            pd += __shfl_down_sync(0xffffffffu, pd, 2, 8);
            pd += __shfl_down_sync(0xffffffffu, pd, 1, 8);
            if ((lane & 7) == 0) {
                g_as1[row * 4 + (lane >> 3)] = ps;
                g_ad1[row * 4 + (lane >> 3)] = pd;
            }
        }
    }
}

// ---------------- CSR build: histogram -> scan -> scatter ------------------
extern "C" __global__ void k_hist(const int* __restrict__ ei) {
    int e = blockIdx.x * blockDim.x + threadIdx.x;
    if (e >= ET) return;
    int d = (e < EE) ? clampN(ei[EE + e]) : (e - EE);
    atomicAdd(&g_deg[d], 1);
}

extern "C" __global__ void k_scan() {
    const int T = 1024;
    const int CH = (NN + T - 1) / T;   // 49
    __shared__ int ssum[T];
    int t = threadIdx.x;
    int base = t * CH;
    int sum = 0;
    for (int i = 0; i < CH; i++) {
        int idx = base + i;
        if (idx < NN) sum += g_deg[idx];
    }
    ssum[t] = sum;
    __syncthreads();
    for (int off = 1; off < T; off <<= 1) {
        int v = (t >= off) ? ssum[t - off] : 0;
        __syncthreads();
        ssum[t] += v;
        __syncthreads();
    }
    int run = ssum[t] - sum;   // exclusive prefix
    for (int i = 0; i < CH; i++) {
        int idx = base + i;
        if (idx < NN) {
            g_rs[idx] = run;
            run += g_deg[idx];
        }
    }
    if (t == T - 1) g_rs[NN] = ssum[T - 1];
}

extern "C" __global__ void k_scatter(const int* __restrict__ ei) {
    int e = blockIdx.x * blockDim.x + threadIdx.x;
    if (e >= ET) return;
    int s, d;
    if (e < EE) { s = clampN(ei[e]); d = clampN(ei[EE + e]); }
    else        { s = d = e - EE; }
    int p = atomicAdd(&g_cur[d], 1);
    g_csr[g_rs[d] + p] = s;
}

// ---------------- layer1 aggregation: warp per dst, pull, 4-wide ILP -------
extern "C" __global__ void k_agg1(const float* __restrict__ b1) {
    int gid = blockIdx.x * blockDim.x + threadIdx.x;
    int d = gid >> 5;
    int lane = gid & 31;
    if (d >= NN) return;
    int head = lane >> 3;
    float ad = g_ad1[d * 4 + head];
    int j = g_rs[d], end = g_rs[d + 1];
    float4 acc = make_float4(0.f, 0.f, 0.f, 0.f);
    float den = 0.f;
    while (j + 3 < end) {
        int s0 = g_csr[j], s1 = g_csr[j + 1], s2 = g_csr[j + 2], s3 = g_csr[j + 3];
        j += 4;
        float a0 = g_as1[s0 * 4 + head];
        float a1 = g_as1[s1 * 4 + head];
        float a2 = g_as1[s2 * 4 + head];
        float a3 = g_as1[s3 * 4 + head];
        float4 h0 = ((const float4*)g_h1)[s0 * 32 + lane];
        float4 h1v = ((const float4*)g_h1)[s1 * 32 + lane];
        float4 h2v = ((const float4*)g_h1)[s2 * 32 + lane];
        float4 h3v = ((const float4*)g_h1)[s3 * 32 + lane];
        float e0 = __expf(lrelu(a0 + ad));
        float e1 = __expf(lrelu(a1 + ad));
        float e2 = __expf(lrelu(a2 + ad));
        float e3 = __expf(lrelu(a3 + ad));
        den += (e0 + e1) + (e2 + e3);
        acc.x += e0 * h0.x + e1 * h1v.x + e2 * h2v.x + e3 * h3v.x;
        acc.y += e0 * h0.y + e1 * h1v.y + e2 * h2v.y + e3 * h3v.y;
        acc.z += e0 * h0.z + e1 * h1v.z + e2 * h2v.z + e3 * h3v.z;
        acc.w += e0 * h0.w + e1 * h1v.w + e2 * h2v.w + e3 * h3v.w;
    }
    while (j < end) {
        int s0 = g_csr[j];
        j++;
        float a0 = g_as1[s0 * 4 + head];
        float4 h0 = ((const float4*)g_h1)[s0 * 32 + lane];
        float e0 = __expf(lrelu(a0 + ad));
        den += e0;
        acc.x += e0 * h0.x;
        acc.y += e0 * h0.y;
        acc.z += e0 * h0.z;
        acc.w += e0 * h0.w;
    }
    float inv = __frcp_rn(den);
    float4 bb = ((const float4*)b1)[lane];
    float4 y;
    y.x = elu1(acc.x * inv + bb.x);
    y.y = elu1(acc.y * inv + bb.y);
    y.z = elu1(acc.z * inv + bb.z);
    y.w = elu1(acc.w * inv + bb.w);
    ((float4*)g_y1)[d * 32 + lane] = y;
}

// ---------------- kernel: h2 = y1 @ W2; as2/ad2 (conflict-free smem) -------
extern "C" __global__ void k_post1(const float* __restrict__ W2,
                                   const float* __restrict__ a_src2,
                                   const float* __restrict__ a_dst2) {
    __shared__ float W2s[128 * 32];   // natural [k][c]
    __shared__ float y_s[8][128];
    int tid = threadIdx.x, warp = tid >> 5, lane = tid & 31;
    for (int i = tid; i < 4096; i += 256)
        W2s[i] = W2[i];
    __syncthreads();
    int node = blockIdx.x * 8 + warp;
    if (node >= NN) return;
    float4 v = ((const float4*)g_y1)[node * 32 + lane];
    ((float4*)(y_s[warp]))[lane] = v;
    __syncwarp();
    float acc = 0.f;
    const float* yr = y_s[warp];
#pragma unroll
    for (int k4 = 0; k4 < 32; k4++) {
        float4 yv = *(const float4*)(yr + k4 * 4);   // broadcast
        acc += yv.x * W2s[(k4 * 4 + 0) * 32 + lane];
        acc += yv.y * W2s[(k4 * 4 + 1) * 32 + lane];
        acc += yv.z * W2s[(k4 * 4 + 2) * 32 + lane];
        acc += yv.w * W2s[(k4 * 4 + 3) * 32 + lane];
    }
    g_h2[node * 32 + lane] = acc;
    float ps = acc * a_src2[lane];
    float pd = acc * a_dst2[lane];
#pragma unroll
    for (int off = 16; off > 0; off >>= 1) {
        ps += __shfl_down_sync(0xffffffffu, ps, off);
        pd += __shfl_down_sync(0xffffffffu, pd, off);
    }
    if (lane == 0) { g_as2[node] = ps; g_ad2[node] = pd; }
}

// ---------------- layer2 aggregation: warp per dst, 4-wide ILP -------------
extern "C" __global__ void k_agg2(const float* __restrict__ b2) {
    int gid = blockIdx.x * blockDim.x + threadIdx.x;
    int d = gid >> 5;
    int lane = gid & 31;
    if (d >= NN) return;
    float ad = g_ad2[d];
    int j = g_rs[d], end = g_rs[d + 1];
    float acc = 0.f, den = 0.f;
    while (j + 3 < end) {
        int s0 = g_csr[j], s1 = g_csr[j + 1], s2 = g_csr[j + 2], s3 = g_csr[j + 3];
        j += 4;
        float a0 = g_as2[s0];
        float a1 = g_as2[s1];
        float a2 = g_as2[s2];
        float a3 = g_as2[s3];
        float h0 = g_h2[s0 * 32 + lane];
        float h1v = g_h2[s1 * 32 + lane];
        float h2v = g_h2[s2 * 32 + lane];
        float h3v = g_h2[s3 * 32 + lane];
        float e0 = __expf(lrelu(a0 + ad));
        float e1 = __expf(lrelu(a1 + ad));
        float e2 = __expf(lrelu(a2 + ad));
        float e3 = __expf(lrelu(a3 + ad));
        den += (e0 + e1) + (e2 + e3);
        acc += e0 * h0 + e1 * h1v + e2 * h2v + e3 * h3v;
    }
    while (j < end) {
        int s0 = g_csr[j];
        j++;
        float a0 = g_as2[s0];
        float h0 = g_h2[s0 * 32 + lane];
        float e0 = __expf(lrelu(a0 + ad));
        den += e0;
        acc += e0 * h0;
    }
    g_z[d * 32 + lane] = elu1(acc * __frcp_rn(den) + b2[lane]);
}

// ---------------- pooling + classifier (block per graph) -------------------
__device__ __forceinline__ int lbound(const int* __restrict__ b, int n, int key) {
    int lo = 0, hi = n;
    while (lo < hi) {
        int m = (lo + hi) >> 1;
        if (b[m] < key) lo = m + 1; else hi = m;
    }
    return lo;
}

extern "C" __global__ void k_poolfinal(const int* __restrict__ batch,
                                       const float* __restrict__ Wc1,
                                       const float* __restrict__ bc1,
                                       const float* __restrict__ Wc2,
                                       const float* __restrict__ bc2,
                                       float* __restrict__ out) {
    __shared__ float ps[4][32];
    int g = blockIdx.x;
    int tid = threadIdx.x, w = tid >> 5, lane = tid & 31;
    int lo = lbound(batch, NN, g);
    int hi = lbound(batch, NN, g + 1);
    float p = 0.f;
    for (int n = lo + w; n < hi; n += 4)
        p += g_z[n * 32 + lane];
    ps[w][lane] = p;
    __syncthreads();
    if (w == 0) {
        p = ps[0][lane] + ps[1][lane] + ps[2][lane] + ps[3][lane];
        int cnt = hi - lo;
        p *= (cnt > 0) ? (1.0f / (float)cnt) : 0.f;
        ps[0][lane] = p;
        __syncwarp();
        float z = 0.f;
        if (lane < 16) {
            z = bc1[lane];
#pragma unroll
            for (int c = 0; c < 32; c++)
                z += ps[0][c] * Wc1[c * 16 + lane];
            z = fmaxf(z, 0.f) * Wc2[lane];
        }
#pragma unroll
        for (int off = 16; off > 0; off >>= 1)
            z += __shfl_down_sync(0xffffffffu, z, off);
        if (lane == 0) out[g] = z + bc2[0];
    }
}

// ---------------- launch -----------------------------------------------------
extern "C" void kernel_launch(void* const* d_in, const int* in_sizes, int n_in,
                              void* d_out, int out_size) {
    const float* x     = (const float*)d_in[0];
    const int*   ei    = (const int*)d_in[1];
    // d_in[2] = edge_attr (unused)
    const int*   batch = (const int*)d_in[3];
    const float* W1   = (const float*)d_in[4];
    const float* as1  = (const float*)d_in[5];
    const float* ad1  = (const float*)d_in[6];
    const float* b1   = (const float*)d_in[7];
    const float* W2   = (const float*)d_in[8];
    const float* as2  = (const float*)d_in[9];
    const float* ad2  = (const float*)d_in[10];
    const float* b2   = (const float*)d_in[11];
    const float* Wc1  = (const float*)d_in[12];
    const float* bc1  = (const float*)d_in[13];
    const float* Wc2  = (const float*)d_in[14];
    const float* bc2  = (const float*)d_in[15];
    float* out = (float*)d_out;

    void *p_deg, *p_cur;
    cudaGetSymbolAddress(&p_deg, g_deg);
    cudaGetSymbolAddress(&p_cur, g_cur);
    cudaMemsetAsync(p_deg, 0, sizeof(int) * NN);
    cudaMemsetAsync(p_cur, 0, sizeof(int) * NN);

    cudaFuncSetAttribute(k_gemm1, cudaFuncAttributeMaxDynamicSharedMemorySize, 98304);

    k_gemm1<<<(NN + 63) / 64, 256, 98304>>>(x, W1, as1, ad1);
    k_hist<<<(ET + 255) / 256, 256>>>(ei);
    k_scan<<<1, 1024>>>();
    k_scatter<<<(ET + 255) / 256, 256>>>(ei);
    {
        long long threads = (long long)NN * 32;
        k_agg1<<<(int)((threads + 255) / 256), 256>>>(b1);
    }
    k_post1<<<(NN + 7) / 8, 256>>>(W2, as2, ad2);
    {
        long long threads = (long long)NN * 32;
        k_agg2<<<(int)((threads + 255) / 256), 256>>>(b2);
    }
    k_poolfinal<<<GG, 128>>>(batch, Wc1, bc1, Wc2, bc2, out);
}